// round 2
// baseline (speedup 1.0000x reference)
#include <cuda_runtime.h>

#define NN 1024
#define DD 128
#define NLAYERS 3

// ---------------- scratch (device globals; no allocation allowed) ----------------
__device__ float g_h  [NN*DD];
__device__ float g_u  [NN*DD];
__device__ float g_v  [NN*DD];
__device__ float g_agg[NN*DD];
__device__ float g_hi [NN*DD];
__device__ float g_hjb[NN*DD];
__device__ float g_partials[32*32];

// ---------------- embed: h = nf @ We + be ----------------
__global__ void embed_kernel(const float* __restrict__ nf,
                             const float* __restrict__ We,
                             const float* __restrict__ be) {
    int idx = blockIdx.x * blockDim.x + threadIdx.x;   // N*D threads
    int i = idx >> 7, d = idx & 127;
    float a0 = nf[3*i], a1 = nf[3*i+1], a2 = nf[3*i+2];
    g_h[idx] = be[d] + a0*We[d] + a1*We[DD + d] + a2*We[2*DD + d];
}

// ---------------- dual-B GEMM: O1 = h@B1 (+b1), O2 = h@B2 (+b2) ----------------
// mode 0: O1=g_u, O2=g_v   mode 1: O1=g_hi, O2=g_hjb
// 128 blocks x 128 threads, 8 rows per block, full 128-col output.
__global__ __launch_bounds__(128) void dualb_kernel(
    const float* __restrict__ B1, const float* __restrict__ B2,
    const float* __restrict__ b1, const float* __restrict__ b2, int mode)
{
    __shared__ float As [8][DD];
    __shared__ float B1s[32][DD];
    __shared__ float B2s[32][DD];

    int tid = threadIdx.x;
    int rb  = blockIdx.x * 8;

    // load 8 rows of h (1024 floats, 2x float4 per thread, coalesced)
#pragma unroll
    for (int e = 0; e < 2; e++) {
        int q = tid + e*128;
        int r = q >> 5, c4 = q & 31;
        ((float4*)As[r])[c4] = ((const float4*)(g_h + (rb + r)*DD))[c4];
    }

    int tr = tid >> 5, tc = tid & 31;
    int r0 = tr*2, r1 = r0 + 1, c0 = tc*4;

    float a1r0[4] = {0,0,0,0}, a1r1[4] = {0,0,0,0};
    float a2r0[4] = {0,0,0,0}, a2r1[4] = {0,0,0,0};

    for (int kb = 0; kb < DD; kb += 32) {
        __syncthreads();
#pragma unroll
        for (int e = 0; e < 8; e++) {
            int q = tid + e*128;
            int k = q >> 5, c4 = q & 31;
            ((float4*)B1s[k])[c4] = ((const float4*)(B1 + (kb + k)*DD))[c4];
            ((float4*)B2s[k])[c4] = ((const float4*)(B2 + (kb + k)*DD))[c4];
        }
        __syncthreads();
#pragma unroll
        for (int kk = 0; kk < 32; kk++) {
            float av0 = As[r0][kb + kk];
            float av1 = As[r1][kb + kk];
            float4 w1 = *(const float4*)&B1s[kk][c0];
            float4 w2 = *(const float4*)&B2s[kk][c0];
            a1r0[0] = fmaf(av0, w1.x, a1r0[0]); a1r0[1] = fmaf(av0, w1.y, a1r0[1]);
            a1r0[2] = fmaf(av0, w1.z, a1r0[2]); a1r0[3] = fmaf(av0, w1.w, a1r0[3]);
            a1r1[0] = fmaf(av1, w1.x, a1r1[0]); a1r1[1] = fmaf(av1, w1.y, a1r1[1]);
            a1r1[2] = fmaf(av1, w1.z, a1r1[2]); a1r1[3] = fmaf(av1, w1.w, a1r1[3]);
            a2r0[0] = fmaf(av0, w2.x, a2r0[0]); a2r0[1] = fmaf(av0, w2.y, a2r0[1]);
            a2r0[2] = fmaf(av0, w2.z, a2r0[2]); a2r0[3] = fmaf(av0, w2.w, a2r0[3]);
            a2r1[0] = fmaf(av1, w2.x, a2r1[0]); a2r1[1] = fmaf(av1, w2.y, a2r1[1]);
            a2r1[2] = fmaf(av1, w2.z, a2r1[2]); a2r1[3] = fmaf(av1, w2.w, a2r1[3]);
        }
    }

    float* O1 = mode ? g_hi  : g_u;
    float* O2 = mode ? g_hjb : g_v;
    float4 bb1 = b1 ? ((const float4*)b1)[tc] : make_float4(0.f,0.f,0.f,0.f);
    float4 bb2 = ((const float4*)b2)[tc];

    float4 o;
    o.x=a1r0[0]+bb1.x; o.y=a1r0[1]+bb1.y; o.z=a1r0[2]+bb1.z; o.w=a1r0[3]+bb1.w;
    ((float4*)(O1 + (rb + r0)*DD))[tc] = o;
    o.x=a1r1[0]+bb1.x; o.y=a1r1[1]+bb1.y; o.z=a1r1[2]+bb1.z; o.w=a1r1[3]+bb1.w;
    ((float4*)(O1 + (rb + r1)*DD))[tc] = o;
    o.x=a2r0[0]+bb2.x; o.y=a2r0[1]+bb2.y; o.z=a2r0[2]+bb2.z; o.w=a2r0[3]+bb2.w;
    ((float4*)(O2 + (rb + r0)*DD))[tc] = o;
    o.x=a2r1[0]+bb2.x; o.y=a2r1[1]+bb2.y; o.z=a2r1[2]+bb2.z; o.w=a2r1[3]+bb2.w;
    ((float4*)(O2 + (rb + r1)*DD))[tc] = o;
}

// ---------------- agg = adj @ v ----------------
// 128 blocks x 256 threads, 8 rows per block (1 row per warp-row-group), K staged in 64-chunks.
__global__ __launch_bounds__(256) void agg_kernel(const float* __restrict__ adj)
{
    __shared__ float adjs[64][9];    // [k][row], padded: conflict-free fill
    __shared__ float vs  [64][DD];   // 32 KB

    int tid = threadIdx.x;
    int rb  = blockIdx.x * 8;
    int tr  = tid >> 5;              // 0..7 -> row
    int tc  = tid & 31;
    int c0  = tc * 4;

    float acc[4] = {0,0,0,0};

    for (int kb = 0; kb < NN; kb += 64) {
        __syncthreads();
#pragma unroll
        for (int e = 0; e < 2; e++) {
            int q = tid + e*256;               // 0..511
            int r = q >> 6, k = q & 63;
            adjs[k][r] = adj[(rb + r)*NN + kb + k];
        }
#pragma unroll
        for (int e = 0; e < 8; e++) {
            int q = tid + e*256;               // 0..2047 float4s
            int k = q >> 5, c4 = q & 31;
            ((float4*)vs[k])[c4] = ((const float4*)(g_v + (kb + k)*DD))[c4];
        }
        __syncthreads();
#pragma unroll
        for (int kk = 0; kk < 64; kk++) {
            float a  = adjs[kk][tr];           // broadcast within warp
            float4 w = *(const float4*)&vs[kk][c0];
            acc[0] = fmaf(a, w.x, acc[0]);
            acc[1] = fmaf(a, w.y, acc[1]);
            acc[2] = fmaf(a, w.z, acc[2]);
            acc[3] = fmaf(a, w.w, acc[3]);
        }
    }
    float4 o = make_float4(acc[0], acc[1], acc[2], acc[3]);
    ((float4*)(g_agg + (rb + tr)*DD))[tc] = o;
}

// ---------------- gate + residual update ----------------
// t = u@W1 + agg@W2 + bg ; h = relu(h + sigmoid(t)*agg)
__global__ __launch_bounds__(128) void gate_kernel(
    const float* __restrict__ W1, const float* __restrict__ W2,
    const float* __restrict__ bgl)
{
    __shared__ float Us [8][DD];
    __shared__ float Gs [8][DD];
    __shared__ float W1s[32][DD];
    __shared__ float W2s[32][DD];

    int tid = threadIdx.x;
    int rb  = blockIdx.x * 8;

#pragma unroll
    for (int e = 0; e < 2; e++) {
        int q = tid + e*128;
        int r = q >> 5, c4 = q & 31;
        ((float4*)Us[r])[c4] = ((const float4*)(g_u   + (rb + r)*DD))[c4];
        ((float4*)Gs[r])[c4] = ((const float4*)(g_agg + (rb + r)*DD))[c4];
    }

    int tr = tid >> 5, tc = tid & 31;
    int r0 = tr*2, r1 = r0 + 1, c0 = tc*4;

    float t0[4] = {0,0,0,0}, t1[4] = {0,0,0,0};

    for (int kb = 0; kb < DD; kb += 32) {
        __syncthreads();
#pragma unroll
        for (int e = 0; e < 8; e++) {
            int q = tid + e*128;
            int k = q >> 5, c4 = q & 31;
            ((float4*)W1s[k])[c4] = ((const float4*)(W1 + (kb + k)*DD))[c4];
            ((float4*)W2s[k])[c4] = ((const float4*)(W2 + (kb + k)*DD))[c4];
        }
        __syncthreads();
#pragma unroll
        for (int kk = 0; kk < 32; kk++) {
            float u0 = Us[r0][kb + kk], u1 = Us[r1][kb + kk];
            float gg0 = Gs[r0][kb + kk], gg1 = Gs[r1][kb + kk];
            float4 w1 = *(const float4*)&W1s[kk][c0];
            float4 w2 = *(const float4*)&W2s[kk][c0];
            t0[0] = fmaf(u0, w1.x, t0[0]); t0[0] = fmaf(gg0, w2.x, t0[0]);
            t0[1] = fmaf(u0, w1.y, t0[1]); t0[1] = fmaf(gg0, w2.y, t0[1]);
            t0[2] = fmaf(u0, w1.z, t0[2]); t0[2] = fmaf(gg0, w2.z, t0[2]);
            t0[3] = fmaf(u0, w1.w, t0[3]); t0[3] = fmaf(gg0, w2.w, t0[3]);
            t1[0] = fmaf(u1, w1.x, t1[0]); t1[0] = fmaf(gg1, w2.x, t1[0]);
            t1[1] = fmaf(u1, w1.y, t1[1]); t1[1] = fmaf(gg1, w2.y, t1[1]);
            t1[2] = fmaf(u1, w1.z, t1[2]); t1[2] = fmaf(gg1, w2.z, t1[2]);
            t1[3] = fmaf(u1, w1.w, t1[3]); t1[3] = fmaf(gg1, w2.w, t1[3]);
        }
    }

    float4 bgv = ((const float4*)bgl)[tc];
    float bga[4] = {bgv.x, bgv.y, bgv.z, bgv.w};

    {
        float4 av = *(const float4*)&Gs[r0][c0];
        float4 hv = ((const float4*)(g_h + (rb + r0)*DD))[tc];
        float avv[4] = {av.x, av.y, av.z, av.w};
        float hvv[4] = {hv.x, hv.y, hv.z, hv.w};
        float outv[4];
#pragma unroll
        for (int j = 0; j < 4; j++) {
            float gv = 1.f / (1.f + __expf(-(t0[j] + bga[j])));
            outv[j] = fmaxf(hvv[j] + gv * avv[j], 0.f);
        }
        ((float4*)(g_h + (rb + r0)*DD))[tc] = make_float4(outv[0],outv[1],outv[2],outv[3]);
    }
    {
        float4 av = *(const float4*)&Gs[r1][c0];
        float4 hv = ((const float4*)(g_h + (rb + r1)*DD))[tc];
        float avv[4] = {av.x, av.y, av.z, av.w};
        float hvv[4] = {hv.x, hv.y, hv.z, hv.w};
        float outv[4];
#pragma unroll
        for (int j = 0; j < 4; j++) {
            float gv = 1.f / (1.f + __expf(-(t1[j] + bga[j])));
            outv[j] = fmaxf(hvv[j] + gv * avv[j], 0.f);
        }
        ((float4*)(g_h + (rb + r1)*DD))[tc] = make_float4(outv[0],outv[1],outv[2],outv[3]);
    }
}

// ---------------- classifier + loss partials ----------------
// logits[i,j] = sum_h relu(hi[i,h] + hjb[j,h]) * w[h] + bc2
// grid (32,32) of 32x32 pair tiles; each thread does a 2x2 pair block.
__global__ __launch_bounds__(256) void cls_kernel(
    const float* __restrict__ Wc2, const float* __restrict__ bc2,
    const float* __restrict__ adj, const float* __restrict__ ew,
    float* __restrict__ out)
{
    __shared__ float hiT[DD][32];   // [h][i]
    __shared__ float hjT[DD][32];   // [h][j]
    __shared__ float w_s[DD];
    __shared__ float red[256];

    int tid = threadIdx.x;
    int ib = blockIdx.y * 32, jb = blockIdx.x * 32;
    int li = tid & 31;
    int hg = (tid >> 5) * 16;       // 16 h-values per 32-thread group

#pragma unroll
    for (int e = 0; e < 4; e++) {
        int h0 = hg + e*4;
        float4 x = *(const float4*)(g_hi  + (ib + li)*DD + h0);
        hiT[h0+0][li] = x.x; hiT[h0+1][li] = x.y; hiT[h0+2][li] = x.z; hiT[h0+3][li] = x.w;
        float4 y = *(const float4*)(g_hjb + (jb + li)*DD + h0);
        hjT[h0+0][li] = y.x; hjT[h0+1][li] = y.y; hjT[h0+2][li] = y.z; hjT[h0+3][li] = y.w;
    }
    if (tid < DD) w_s[tid] = Wc2[tid];
    __syncthreads();

    int i0 = (tid >> 4) * 2;        // 0..30
    int j0 = (tid & 15) * 2;        // 0..30

    float a00 = 0.f, a01 = 0.f, a10 = 0.f, a11 = 0.f;
#pragma unroll
    for (int h = 0; h < DD; h++) {
        float2 a = *(const float2*)&hiT[h][i0];
        float2 b = *(const float2*)&hjT[h][j0];
        float w  = w_s[h];
        a00 = fmaf(fmaxf(a.x + b.x, 0.f), w, a00);
        a01 = fmaf(fmaxf(a.x + b.y, 0.f), w, a01);
        a10 = fmaf(fmaxf(a.y + b.x, 0.f), w, a10);
        a11 = fmaf(fmaxf(a.y + b.y, 0.f), w, a11);
    }

    float bc = bc2[0];
    float lsum = 0.f;
    {
        int i = ib + i0, j = jb + j0;
        float2 lg0 = make_float2(a00 + bc, a01 + bc);
        float2 lg1 = make_float2(a10 + bc, a11 + bc);
        *(float2*)&out[i*NN + j]       = lg0;
        *(float2*)&out[(i+1)*NN + j]   = lg1;
        float2 ad0 = *(const float2*)&adj[i*NN + j];
        float2 ad1 = *(const float2*)&adj[(i+1)*NN + j];
        float2 ew0 = *(const float2*)&ew [i*NN + j];
        float2 ew1 = *(const float2*)&ew [(i+1)*NN + j];
        float d;
        d = lg0.x*ad0.x - ew0.x; lsum = fmaf(d, d, lsum);
        d = lg0.y*ad0.y - ew0.y; lsum = fmaf(d, d, lsum);
        d = lg1.x*ad1.x - ew1.x; lsum = fmaf(d, d, lsum);
        d = lg1.y*ad1.y - ew1.y; lsum = fmaf(d, d, lsum);
    }

    red[tid] = lsum;
    __syncthreads();
#pragma unroll
    for (int s = 128; s > 0; s >>= 1) {
        if (tid < s) red[tid] += red[tid + s];
        __syncthreads();
    }
    if (tid == 0) g_partials[blockIdx.y * 32 + blockIdx.x] = red[0];
}

// ---------------- deterministic loss reduce ----------------
__global__ void loss_kernel(float* __restrict__ out_loss)
{
    __shared__ float red[256];
    int tid = threadIdx.x;
    float s = 0.f;
    for (int k = tid; k < 1024; k += 256) s += g_partials[k];
    red[tid] = s;
    __syncthreads();
#pragma unroll
    for (int t = 128; t > 0; t >>= 1) {
        if (tid < t) red[tid] += red[tid + t];
        __syncthreads();
    }
    if (tid == 0) out_loss[0] = red[0] * (1.f / ((float)NN * (float)NN));
}

// ---------------- launch ----------------
extern "C" void kernel_launch(void* const* d_in, const int* in_sizes, int n_in,
                              void* d_out, int out_size)
{
    const float* nf   = (const float*)d_in[0];
    const float* adj  = (const float*)d_in[1];
    const float* ew   = (const float*)d_in[2];
    const float* We   = (const float*)d_in[3];
    const float* be   = (const float*)d_in[4];
    const float* Wu   = (const float*)d_in[5];
    const float* bu   = (const float*)d_in[6];
    const float* Wv   = (const float*)d_in[7];
    const float* bv   = (const float*)d_in[8];
    const float* Wg   = (const float*)d_in[9];
    const float* bg   = (const float*)d_in[10];
    const float* Wc1  = (const float*)d_in[11];
    const float* bc1  = (const float*)d_in[12];
    const float* Wc2  = (const float*)d_in[13];
    const float* bc2  = (const float*)d_in[14];
    float* out = (float*)d_out;

    embed_kernel<<<NN*DD/256, 256>>>(nf, We, be);

    for (int l = 0; l < NLAYERS; l++) {
        dualb_kernel<<<128, 128>>>(Wu + l*DD*DD, Wv + l*DD*DD,
                                   bu + l*DD,    bv + l*DD, 0);
        agg_kernel<<<128, 256>>>(adj);
        gate_kernel<<<128, 128>>>(Wg + l*2*DD*DD, Wg + l*2*DD*DD + DD*DD,
                                  bg + l*DD);
    }

    // hi = h@Wc1[:D], hjb = h@Wc1[D:] + bc1
    dualb_kernel<<<128, 128>>>(Wc1, Wc1 + DD*DD, nullptr, bc1, 1);

    cls_kernel<<<dim3(32, 32), 256>>>(Wc2, bc2, adj, ew, out);

    if (out_size > NN*NN) {
        loss_kernel<<<1, 256>>>(out + NN*NN);
    }
}

// round 3
// speedup vs baseline: 1.0018x; 1.0018x over previous
#include <cuda_runtime.h>

#define NN 1024
#define DD 128
#define NLAYERS 3

// ---------------- scratch (device globals; no allocation allowed) ----------------
__device__ float g_h  [NN*DD];
__device__ float g_u  [NN*DD];
__device__ float g_v  [NN*DD];
__device__ float g_agg[NN*DD];
__device__ float g_hi [NN*DD];
__device__ float g_hjb[NN*DD];
__device__ float g_partials[32*32];

// ---------------- embed: h = nf @ We + be ----------------
__global__ void embed_kernel(const float* __restrict__ nf,
                             const float* __restrict__ We,
                             const float* __restrict__ be) {
    int idx = blockIdx.x * blockDim.x + threadIdx.x;   // N*D threads
    int i = idx >> 7, d = idx & 127;
    float a0 = nf[3*i], a1 = nf[3*i+1], a2 = nf[3*i+2];
    g_h[idx] = be[d] + a0*We[d] + a1*We[DD + d] + a2*We[2*DD + d];
}

// ---------------- dual-B GEMM: O1 = h@B1 (+b1), O2 = h@B2 (+b2) ----------------
// mode 0: O1=g_u, O2=g_v   mode 1: O1=g_hi, O2=g_hjb
// 128 blocks x 128 threads, 8 rows per block, full 128-col output.
__global__ __launch_bounds__(128) void dualb_kernel(
    const float* __restrict__ B1, const float* __restrict__ B2,
    const float* __restrict__ b1, const float* __restrict__ b2, int mode)
{
    __shared__ float As [8][DD];
    __shared__ float B1s[32][DD];
    __shared__ float B2s[32][DD];

    int tid = threadIdx.x;
    int rb  = blockIdx.x * 8;

    // load 8 rows of h (1024 floats, 2x float4 per thread, coalesced)
#pragma unroll
    for (int e = 0; e < 2; e++) {
        int q = tid + e*128;
        int r = q >> 5, c4 = q & 31;
        ((float4*)As[r])[c4] = ((const float4*)(g_h + (rb + r)*DD))[c4];
    }

    int tr = tid >> 5, tc = tid & 31;
    int r0 = tr*2, r1 = r0 + 1, c0 = tc*4;

    float a1r0[4] = {0,0,0,0}, a1r1[4] = {0,0,0,0};
    float a2r0[4] = {0,0,0,0}, a2r1[4] = {0,0,0,0};

    for (int kb = 0; kb < DD; kb += 32) {
        __syncthreads();
#pragma unroll
        for (int e = 0; e < 8; e++) {
            int q = tid + e*128;
            int k = q >> 5, c4 = q & 31;
            ((float4*)B1s[k])[c4] = ((const float4*)(B1 + (kb + k)*DD))[c4];
            ((float4*)B2s[k])[c4] = ((const float4*)(B2 + (kb + k)*DD))[c4];
        }
        __syncthreads();
#pragma unroll
        for (int kk = 0; kk < 32; kk++) {
            float av0 = As[r0][kb + kk];
            float av1 = As[r1][kb + kk];
            float4 w1 = *(const float4*)&B1s[kk][c0];
            float4 w2 = *(const float4*)&B2s[kk][c0];
            a1r0[0] = fmaf(av0, w1.x, a1r0[0]); a1r0[1] = fmaf(av0, w1.y, a1r0[1]);
            a1r0[2] = fmaf(av0, w1.z, a1r0[2]); a1r0[3] = fmaf(av0, w1.w, a1r0[3]);
            a1r1[0] = fmaf(av1, w1.x, a1r1[0]); a1r1[1] = fmaf(av1, w1.y, a1r1[1]);
            a1r1[2] = fmaf(av1, w1.z, a1r1[2]); a1r1[3] = fmaf(av1, w1.w, a1r1[3]);
            a2r0[0] = fmaf(av0, w2.x, a2r0[0]); a2r0[1] = fmaf(av0, w2.y, a2r0[1]);
            a2r0[2] = fmaf(av0, w2.z, a2r0[2]); a2r0[3] = fmaf(av0, w2.w, a2r0[3]);
            a2r1[0] = fmaf(av1, w2.x, a2r1[0]); a2r1[1] = fmaf(av1, w2.y, a2r1[1]);
            a2r1[2] = fmaf(av1, w2.z, a2r1[2]); a2r1[3] = fmaf(av1, w2.w, a2r1[3]);
        }
    }

    float* O1 = mode ? g_hi  : g_u;
    float* O2 = mode ? g_hjb : g_v;
    float4 bb1 = b1 ? ((const float4*)b1)[tc] : make_float4(0.f,0.f,0.f,0.f);
    float4 bb2 = ((const float4*)b2)[tc];

    float4 o;
    o.x=a1r0[0]+bb1.x; o.y=a1r0[1]+bb1.y; o.z=a1r0[2]+bb1.z; o.w=a1r0[3]+bb1.w;
    ((float4*)(O1 + (rb + r0)*DD))[tc] = o;
    o.x=a1r1[0]+bb1.x; o.y=a1r1[1]+bb1.y; o.z=a1r1[2]+bb1.z; o.w=a1r1[3]+bb1.w;
    ((float4*)(O1 + (rb + r1)*DD))[tc] = o;
    o.x=a2r0[0]+bb2.x; o.y=a2r0[1]+bb2.y; o.z=a2r0[2]+bb2.z; o.w=a2r0[3]+bb2.w;
    ((float4*)(O2 + (rb + r0)*DD))[tc] = o;
    o.x=a2r1[0]+bb2.x; o.y=a2r1[1]+bb2.y; o.z=a2r1[2]+bb2.z; o.w=a2r1[3]+bb2.w;
    ((float4*)(O2 + (rb + r1)*DD))[tc] = o;
}

// ---------------- agg = adj @ v ----------------
// 128 blocks x 256 threads, 8 rows per block (1 row per warp-row-group), K staged in 64-chunks.
__global__ __launch_bounds__(256) void agg_kernel(const float* __restrict__ adj)
{
    __shared__ float adjs[64][9];    // [k][row], padded: conflict-free fill
    __shared__ float vs  [64][DD];   // 32 KB

    int tid = threadIdx.x;
    int rb  = blockIdx.x * 8;
    int tr  = tid >> 5;              // 0..7 -> row
    int tc  = tid & 31;
    int c0  = tc * 4;

    float acc[4] = {0,0,0,0};

    for (int kb = 0; kb < NN; kb += 64) {
        __syncthreads();
#pragma unroll
        for (int e = 0; e < 2; e++) {
            int q = tid + e*256;               // 0..511
            int r = q >> 6, k = q & 63;
            adjs[k][r] = adj[(rb + r)*NN + kb + k];
        }
#pragma unroll
        for (int e = 0; e < 8; e++) {
            int q = tid + e*256;               // 0..2047 float4s
            int k = q >> 5, c4 = q & 31;
            ((float4*)vs[k])[c4] = ((const float4*)(g_v + (kb + k)*DD))[c4];
        }
        __syncthreads();
#pragma unroll
        for (int kk = 0; kk < 64; kk++) {
            float a  = adjs[kk][tr];           // broadcast within warp
            float4 w = *(const float4*)&vs[kk][c0];
            acc[0] = fmaf(a, w.x, acc[0]);
            acc[1] = fmaf(a, w.y, acc[1]);
            acc[2] = fmaf(a, w.z, acc[2]);
            acc[3] = fmaf(a, w.w, acc[3]);
        }
    }
    float4 o = make_float4(acc[0], acc[1], acc[2], acc[3]);
    ((float4*)(g_agg + (rb + tr)*DD))[tc] = o;
}

// ---------------- gate + residual update ----------------
// t = u@W1 + agg@W2 + bg ; h = relu(h + sigmoid(t)*agg)
__global__ __launch_bounds__(128) void gate_kernel(
    const float* __restrict__ W1, const float* __restrict__ W2,
    const float* __restrict__ bgl)
{
    __shared__ float Us [8][DD];
    __shared__ float Gs [8][DD];
    __shared__ float W1s[32][DD];
    __shared__ float W2s[32][DD];

    int tid = threadIdx.x;
    int rb  = blockIdx.x * 8;

#pragma unroll
    for (int e = 0; e < 2; e++) {
        int q = tid + e*128;
        int r = q >> 5, c4 = q & 31;
        ((float4*)Us[r])[c4] = ((const float4*)(g_u   + (rb + r)*DD))[c4];
        ((float4*)Gs[r])[c4] = ((const float4*)(g_agg + (rb + r)*DD))[c4];
    }

    int tr = tid >> 5, tc = tid & 31;
    int r0 = tr*2, r1 = r0 + 1, c0 = tc*4;

    float t0[4] = {0,0,0,0}, t1[4] = {0,0,0,0};

    for (int kb = 0; kb < DD; kb += 32) {
        __syncthreads();
#pragma unroll
        for (int e = 0; e < 8; e++) {
            int q = tid + e*128;
            int k = q >> 5, c4 = q & 31;
            ((float4*)W1s[k])[c4] = ((const float4*)(W1 + (kb + k)*DD))[c4];
            ((float4*)W2s[k])[c4] = ((const float4*)(W2 + (kb + k)*DD))[c4];
        }
        __syncthreads();
#pragma unroll
        for (int kk = 0; kk < 32; kk++) {
            float u0 = Us[r0][kb + kk], u1 = Us[r1][kb + kk];
            float gg0 = Gs[r0][kb + kk], gg1 = Gs[r1][kb + kk];
            float4 w1 = *(const float4*)&W1s[kk][c0];
            float4 w2 = *(const float4*)&W2s[kk][c0];
            t0[0] = fmaf(u0, w1.x, t0[0]); t0[0] = fmaf(gg0, w2.x, t0[0]);
            t0[1] = fmaf(u0, w1.y, t0[1]); t0[1] = fmaf(gg0, w2.y, t0[1]);
            t0[2] = fmaf(u0, w1.z, t0[2]); t0[2] = fmaf(gg0, w2.z, t0[2]);
            t0[3] = fmaf(u0, w1.w, t0[3]); t0[3] = fmaf(gg0, w2.w, t0[3]);
            t1[0] = fmaf(u1, w1.x, t1[0]); t1[0] = fmaf(gg1, w2.x, t1[0]);
            t1[1] = fmaf(u1, w1.y, t1[1]); t1[1] = fmaf(gg1, w2.y, t1[1]);
            t1[2] = fmaf(u1, w1.z, t1[2]); t1[2] = fmaf(gg1, w2.z, t1[2]);
            t1[3] = fmaf(u1, w1.w, t1[3]); t1[3] = fmaf(gg1, w2.w, t1[3]);
        }
    }

    float4 bgv = ((const float4*)bgl)[tc];
    float bga[4] = {bgv.x, bgv.y, bgv.z, bgv.w};

    {
        float4 av = *(const float4*)&Gs[r0][c0];
        float4 hv = ((const float4*)(g_h + (rb + r0)*DD))[tc];
        float avv[4] = {av.x, av.y, av.z, av.w};
        float hvv[4] = {hv.x, hv.y, hv.z, hv.w};
        float outv[4];
#pragma unroll
        for (int j = 0; j < 4; j++) {
            float gv = 1.f / (1.f + __expf(-(t0[j] + bga[j])));
            outv[j] = fmaxf(hvv[j] + gv * avv[j], 0.f);
        }
        ((float4*)(g_h + (rb + r0)*DD))[tc] = make_float4(outv[0],outv[1],outv[2],outv[3]);
    }
    {
        float4 av = *(const float4*)&Gs[r1][c0];
        float4 hv = ((const float4*)(g_h + (rb + r1)*DD))[tc];
        float avv[4] = {av.x, av.y, av.z, av.w};
        float hvv[4] = {hv.x, hv.y, hv.z, hv.w};
        float outv[4];
#pragma unroll
        for (int j = 0; j < 4; j++) {
            float gv = 1.f / (1.f + __expf(-(t1[j] + bga[j])));
            outv[j] = fmaxf(hvv[j] + gv * avv[j], 0.f);
        }
        ((float4*)(g_h + (rb + r1)*DD))[tc] = make_float4(outv[0],outv[1],outv[2],outv[3]);
    }
}

// ---------------- classifier + loss partials ----------------
// logits[i,j] = sum_h relu(hi[i,h] + hjb[j,h]) * w[h] + bc2
// grid (32,32) of 32x32 pair tiles; each thread does a 2x2 pair block.
__global__ __launch_bounds__(256) void cls_kernel(
    const float* __restrict__ Wc2, const float* __restrict__ bc2,
    const float* __restrict__ adj, const float* __restrict__ ew,
    float* __restrict__ out)
{
    __shared__ float hiT[DD][32];   // [h][i]
    __shared__ float hjT[DD][32];   // [h][j]
    __shared__ float w_s[DD];
    __shared__ float red[256];

    int tid = threadIdx.x;
    int ib = blockIdx.y * 32, jb = blockIdx.x * 32;
    int li = tid & 31;
    int hg = (tid >> 5) * 16;       // 16 h-values per 32-thread group

#pragma unroll
    for (int e = 0; e < 4; e++) {
        int h0 = hg + e*4;
        float4 x = *(const float4*)(g_hi  + (ib + li)*DD + h0);
        hiT[h0+0][li] = x.x; hiT[h0+1][li] = x.y; hiT[h0+2][li] = x.z; hiT[h0+3][li] = x.w;
        float4 y = *(const float4*)(g_hjb + (jb + li)*DD + h0);
        hjT[h0+0][li] = y.x; hjT[h0+1][li] = y.y; hjT[h0+2][li] = y.z; hjT[h0+3][li] = y.w;
    }
    if (tid < DD) w_s[tid] = Wc2[tid];
    __syncthreads();

    int i0 = (tid >> 4) * 2;        // 0..30
    int j0 = (tid & 15) * 2;        // 0..30

    float a00 = 0.f, a01 = 0.f, a10 = 0.f, a11 = 0.f;
#pragma unroll
    for (int h = 0; h < DD; h++) {
        float2 a = *(const float2*)&hiT[h][i0];
        float2 b = *(const float2*)&hjT[h][j0];
        float w  = w_s[h];
        a00 = fmaf(fmaxf(a.x + b.x, 0.f), w, a00);
        a01 = fmaf(fmaxf(a.x + b.y, 0.f), w, a01);
        a10 = fmaf(fmaxf(a.y + b.x, 0.f), w, a10);
        a11 = fmaf(fmaxf(a.y + b.y, 0.f), w, a11);
    }

    float bc = bc2[0];
    float lsum = 0.f;
    {
        int i = ib + i0, j = jb + j0;
        float2 lg0 = make_float2(a00 + bc, a01 + bc);
        float2 lg1 = make_float2(a10 + bc, a11 + bc);
        *(float2*)&out[i*NN + j]       = lg0;
        *(float2*)&out[(i+1)*NN + j]   = lg1;
        float2 ad0 = *(const float2*)&adj[i*NN + j];
        float2 ad1 = *(const float2*)&adj[(i+1)*NN + j];
        float2 ew0 = *(const float2*)&ew [i*NN + j];
        float2 ew1 = *(const float2*)&ew [(i+1)*NN + j];
        float d;
        d = lg0.x*ad0.x - ew0.x; lsum = fmaf(d, d, lsum);
        d = lg0.y*ad0.y - ew0.y; lsum = fmaf(d, d, lsum);
        d = lg1.x*ad1.x - ew1.x; lsum = fmaf(d, d, lsum);
        d = lg1.y*ad1.y - ew1.y; lsum = fmaf(d, d, lsum);
    }

    red[tid] = lsum;
    __syncthreads();
#pragma unroll
    for (int s = 128; s > 0; s >>= 1) {
        if (tid < s) red[tid] += red[tid + s];
        __syncthreads();
    }
    if (tid == 0) g_partials[blockIdx.y * 32 + blockIdx.x] = red[0];
}

// ---------------- deterministic loss reduce ----------------
__global__ void loss_kernel(float* __restrict__ out_loss)
{
    __shared__ float red[256];
    int tid = threadIdx.x;
    float s = 0.f;
    for (int k = tid; k < 1024; k += 256) s += g_partials[k];
    red[tid] = s;
    __syncthreads();
#pragma unroll
    for (int t = 128; t > 0; t >>= 1) {
        if (tid < t) red[tid] += red[tid + t];
        __syncthreads();
    }
    if (tid == 0) out_loss[0] = red[0] * (1.f / ((float)NN * (float)NN));
}

// ---------------- launch ----------------
extern "C" void kernel_launch(void* const* d_in, const int* in_sizes, int n_in,
                              void* d_out, int out_size)
{
    const float* nf   = (const float*)d_in[0];
    const float* adj  = (const float*)d_in[1];
    const float* ew   = (const float*)d_in[2];
    const float* We   = (const float*)d_in[3];
    const float* be   = (const float*)d_in[4];
    const float* Wu   = (const float*)d_in[5];
    const float* bu   = (const float*)d_in[6];
    const float* Wv   = (const float*)d_in[7];
    const float* bv   = (const float*)d_in[8];
    const float* Wg   = (const float*)d_in[9];
    const float* bg   = (const float*)d_in[10];
    const float* Wc1  = (const float*)d_in[11];
    const float* bc1  = (const float*)d_in[12];
    const float* Wc2  = (const float*)d_in[13];
    const float* bc2  = (const float*)d_in[14];
    float* out = (float*)d_out;

    embed_kernel<<<NN*DD/256, 256>>>(nf, We, be);

    for (int l = 0; l < NLAYERS; l++) {
        dualb_kernel<<<128, 128>>>(Wu + l*DD*DD, Wv + l*DD*DD,
                                   bu + l*DD,    bv + l*DD, 0);
        agg_kernel<<<128, 256>>>(adj);
        gate_kernel<<<128, 128>>>(Wg + l*2*DD*DD, Wg + l*2*DD*DD + DD*DD,
                                  bg + l*DD);
    }

    // hi = h@Wc1[:D], hjb = h@Wc1[D:] + bc1
    dualb_kernel<<<128, 128>>>(Wc1, Wc1 + DD*DD, nullptr, bc1, 1);

    cls_kernel<<<dim3(32, 32), 256>>>(Wc2, bc2, adj, ew, out);

    if (out_size > NN*NN) {
        loss_kernel<<<1, 256>>>(out + NN*NN);
    }
}

// round 4
// speedup vs baseline: 1.3623x; 1.3599x over previous
#include <cuda_runtime.h>

#define NN 1024
#define DD 128
#define NLAYERS 3

typedef unsigned long long u64;

// ---------------- f32x2 helpers ----------------
__device__ __forceinline__ u64 pack2(float x, float y){ u64 r; asm("mov.b64 %0,{%1,%2};":"=l"(r):"f"(x),"f"(y)); return r; }
__device__ __forceinline__ u64 dup2(float x){ return pack2(x, x); }
__device__ __forceinline__ u64 fma2(u64 a, u64 b, u64 c){ u64 d; asm("fma.rn.f32x2 %0,%1,%2,%3;":"=l"(d):"l"(a),"l"(b),"l"(c)); return d; }
__device__ __forceinline__ u64 add2(u64 a, u64 b){ u64 d; asm("add.rn.f32x2 %0,%1,%2;":"=l"(d):"l"(a),"l"(b)); return d; }
__device__ __forceinline__ float2 unpk(u64 x){ float2 f; asm("mov.b64 {%0,%1},%2;":"=f"(f.x),"=f"(f.y):"l"(x)); return f; }

// ---------------- scratch ----------------
__device__ float g_h  [NN*DD];
__device__ float g_u  [NN*DD];
__device__ float g_v  [NN*DD];
__device__ float g_agg[NN*DD];
__device__ float g_hi [NN*DD];
__device__ float g_hjb[NN*DD];
__device__ float g_si [NN];
__device__ float g_sj [NN];
__device__ float g_P  [4*NN*DD];
__device__ float g_part[256];

// ---------------- embed: h = nf @ We + be ----------------
__global__ void embed_kernel(const float* __restrict__ nf,
                             const float* __restrict__ We,
                             const float* __restrict__ be) {
    int idx = blockIdx.x * blockDim.x + threadIdx.x;
    int i = idx >> 7, d = idx & 127;
    float a0 = nf[3*i], a1 = nf[3*i+1], a2 = nf[3*i+2];
    g_h[idx] = be[d] + a0*We[d] + a1*We[DD + d] + a2*We[2*DD + d];
}

// ---------------- generic GEMM: O = A @ B (+bias) ----------------
// Block tile 32 rows x 128 cols, 128 threads, thread tile 4r x 8c, f32x2 accum.
// A is [M x K] (lda given), split across A1/A2 at k=asplit (for gate's concat).
// blockIdx.y selects (B1,bias1,O1)/(B2,bias2,O2). blockIdx.z = split-K chunk of klen;
// if gridDim.z>1 writes raw partials at O + z*NN*DD (no bias).
__global__ __launch_bounds__(128, 4) void gemm_kernel(
    const float* __restrict__ A1, const float* __restrict__ A2, int asplit, int lda,
    const float* __restrict__ B1, const float* __restrict__ B2,
    const float* __restrict__ bias1, const float* __restrict__ bias2,
    float* __restrict__ O1, float* __restrict__ O2, int klen)
{
    __shared__ float As[32][36];    // [k][row], transposed
    __shared__ float Bs[32][128];   // [k][col]

    int t  = threadIdx.x;
    int rb = blockIdx.x * 32;
    const float* B    = blockIdx.y ? B2    : B1;
    const float* bias = blockIdx.y ? bias2 : bias1;
    float*       O    = blockIdx.y ? O2    : O1;
    int kstart = blockIdx.z * klen;

    int rowg = t >> 4, colg = t & 15;
    int r0 = rowg * 4, c0 = colg * 8;

    u64 acc[4][4];
#pragma unroll
    for (int r = 0; r < 4; r++)
#pragma unroll
        for (int c = 0; c < 4; c++) acc[r][c] = 0ull;

    for (int kb = kstart; kb < kstart + klen; kb += 32) {
        const float* A = A1; int ka = kb;
        if (kb >= asplit) { A = A2; ka = kb - asplit; }
        __syncthreads();
        // stage A chunk transposed: 32 rows x 32 k
#pragma unroll
        for (int e = 0; e < 2; e++) {
            int idx = e*128 + t;           // 256 float4
            int r = idx >> 3, f4 = idx & 7;
            float4 v = *(const float4*)&A[(size_t)(rb + r)*lda + ka + f4*4];
            As[f4*4+0][r] = v.x; As[f4*4+1][r] = v.y;
            As[f4*4+2][r] = v.z; As[f4*4+3][r] = v.w;
        }
        // stage B chunk: 32 k x 128 cols
#pragma unroll
        for (int e = 0; e < 8; e++) {
            int idx = e*128 + t;           // 1024 float4
            int k = idx >> 5, c4 = idx & 31;
            *(float4*)&Bs[k][c4*4] = *(const float4*)&B[(size_t)(kb + k)*DD + c4*4];
        }
        __syncthreads();
#pragma unroll 8
        for (int k = 0; k < 32; k++) {
            float4 a4 = *(const float4*)&As[k][r0];
            ulonglong2 bx = *(const ulonglong2*)&Bs[k][c0];
            ulonglong2 by = *(const ulonglong2*)&Bs[k][c0+4];
            u64 d0 = dup2(a4.x), d1 = dup2(a4.y), d2 = dup2(a4.z), d3 = dup2(a4.w);
            acc[0][0]=fma2(d0,bx.x,acc[0][0]); acc[0][1]=fma2(d0,bx.y,acc[0][1]);
            acc[0][2]=fma2(d0,by.x,acc[0][2]); acc[0][3]=fma2(d0,by.y,acc[0][3]);
            acc[1][0]=fma2(d1,bx.x,acc[1][0]); acc[1][1]=fma2(d1,bx.y,acc[1][1]);
            acc[1][2]=fma2(d1,by.x,acc[1][2]); acc[1][3]=fma2(d1,by.y,acc[1][3]);
            acc[2][0]=fma2(d2,bx.x,acc[2][0]); acc[2][1]=fma2(d2,bx.y,acc[2][1]);
            acc[2][2]=fma2(d2,by.x,acc[2][2]); acc[2][3]=fma2(d2,by.y,acc[2][3]);
            acc[3][0]=fma2(d3,bx.x,acc[3][0]); acc[3][1]=fma2(d3,bx.y,acc[3][1]);
            acc[3][2]=fma2(d3,by.x,acc[3][2]); acc[3][3]=fma2(d3,by.y,acc[3][3]);
        }
    }

    if (gridDim.z == 1) {
        u64 bb[4] = {0ull,0ull,0ull,0ull};
        if (bias) {
            float4 u = *(const float4*)&bias[c0];
            float4 v = *(const float4*)&bias[c0+4];
            bb[0] = pack2(u.x,u.y); bb[1] = pack2(u.z,u.w);
            bb[2] = pack2(v.x,v.y); bb[3] = pack2(v.z,v.w);
        }
#pragma unroll
        for (int r = 0; r < 4; r++) {
            float* dst = O + (size_t)(rb + r0 + r)*DD + c0;
            ulonglong2 s1; s1.x = add2(acc[r][0], bb[0]); s1.y = add2(acc[r][1], bb[1]);
            ulonglong2 s2; s2.x = add2(acc[r][2], bb[2]); s2.y = add2(acc[r][3], bb[3]);
            *(ulonglong2*)dst       = s1;
            *(ulonglong2*)(dst + 4) = s2;
        }
    } else {
        float* P = O + (size_t)blockIdx.z * (NN*DD);
#pragma unroll
        for (int r = 0; r < 4; r++) {
            float* dst = P + (size_t)(rb + r0 + r)*DD + c0;
            ulonglong2 s1; s1.x = acc[r][0]; s1.y = acc[r][1];
            ulonglong2 s2; s2.x = acc[r][2]; s2.y = acc[r][3];
            *(ulonglong2*)dst       = s1;
            *(ulonglong2*)(dst + 4) = s2;
        }
    }
}

// ---------------- agg reduce: g_agg = sum of 4 split-K partials ----------------
__global__ void agg_red_kernel() {
    int idx = blockIdx.x * blockDim.x + threadIdx.x;   // float4 index
    const float4* P0 = (const float4*)g_P;
    const float4* P1 = (const float4*)(g_P + NN*DD);
    const float4* P2 = (const float4*)(g_P + 2*NN*DD);
    const float4* P3 = (const float4*)(g_P + 3*NN*DD);
    float4 a = P0[idx], b = P1[idx], c = P2[idx], d = P3[idx];
    float4 o;
    o.x = (a.x + b.x) + (c.x + d.x);
    o.y = (a.y + b.y) + (c.y + d.y);
    o.z = (a.z + b.z) + (c.z + d.z);
    o.w = (a.w + b.w) + (c.w + d.w);
    ((float4*)g_agg)[idx] = o;
}

// ---------------- gate finish: t=P0+P1+bg; h = relu(h + sigmoid(t)*agg) ----------------
__global__ void gate_fin_kernel(const float* __restrict__ bg) {
    int idx = blockIdx.x * blockDim.x + threadIdx.x;   // float4 index over NN*DD/4
    int c4 = idx & 31;
    float4 p0 = ((const float4*)g_P)[idx];
    float4 p1 = ((const float4*)(g_P + NN*DD))[idx];
    float4 bgv = ((const float4*)bg)[c4];
    float4 ag  = ((const float4*)g_agg)[idx];
    float4 hv  = ((const float4*)g_h)[idx];
    float tt[4] = {p0.x+p1.x+bgv.x, p0.y+p1.y+bgv.y, p0.z+p1.z+bgv.z, p0.w+p1.w+bgv.w};
    float aa[4] = {ag.x, ag.y, ag.z, ag.w};
    float hh[4] = {hv.x, hv.y, hv.z, hv.w};
    float oo[4];
#pragma unroll
    for (int j = 0; j < 4; j++) {
        float g = 1.f / (1.f + __expf(-tt[j]));
        oo[j] = fmaxf(hh[j] + g * aa[j], 0.f);
    }
    ((float4*)g_h)[idx] = make_float4(oo[0], oo[1], oo[2], oo[3]);
}

// ---------------- si/sj: rank-1 classifier precompute ----------------
// si[i] = 0.5*sum_h hi[i,h]*w[h] ; sj[j] = 0.5*sum_h hjb[j,h]*w[h] + bc2
__global__ void sisj_kernel(const float* __restrict__ Wc2, const float* __restrict__ bc2) {
    int t = threadIdx.x;
    int w = t >> 5, lane = t & 31;
    int row = blockIdx.x * 8 + w;
    const float* src = blockIdx.y ? g_hjb : g_hi;
    float4 v  = *(const float4*)&src[(size_t)row*DD + lane*4];
    float4 wv = *(const float4*)&Wc2[lane*4];
    float s = v.x*wv.x + v.y*wv.y + v.z*wv.z + v.w*wv.w;
#pragma unroll
    for (int o = 16; o > 0; o >>= 1) s += __shfl_xor_sync(0xffffffffu, s, o);
    if (lane == 0) {
        if (blockIdx.y) g_sj[row] = 0.5f*s + bc2[0];
        else            g_si[row] = 0.5f*s;
    }
}

// ---------------- classifier + loss partials ----------------
// logits[i,j] = si[i] + sj[j] + sum_h |hi[i,h]+hjb[j,h]| * 0.5*w[h]
// 64x64 pair tile per block, 256 threads, thread tile 4i x 4j strided by 16.
__global__ __launch_bounds__(256, 2) void cls_kernel(
    const float* __restrict__ Wc2,
    const float* __restrict__ adj, const float* __restrict__ ew,
    float* __restrict__ out)
{
    __shared__ float hiS[64][34];
    __shared__ float hjS[64][34];
    __shared__ u64   wsS[64];
    __shared__ float siS[64], sjS[64];
    __shared__ float red[256];

    int t  = threadIdx.x;
    int ib = blockIdx.y * 64, jb = blockIdx.x * 64;

    if (t < 64)       siS[t]      = g_si[ib + t];
    else if (t < 128) sjS[t - 64] = g_sj[jb + t - 64];
    else if (t < 192) {
        int h2 = t - 128;
        wsS[h2] = pack2(0.5f*Wc2[2*h2], 0.5f*Wc2[2*h2+1]);
    }

    int ig = t >> 4, jg = t & 15;
    const u64 amask = 0x7FFFFFFF7FFFFFFFull;

    u64 acc[4][4];
#pragma unroll
    for (int a = 0; a < 4; a++)
#pragma unroll
        for (int b = 0; b < 4; b++) acc[a][b] = 0ull;

    for (int hc = 0; hc < DD; hc += 32) {
        __syncthreads();
#pragma unroll
        for (int e = 0; e < 4; e++) {
            int idx = e*256 + t;           // 1024 float2 per matrix
            int r = idx >> 4, q = (idx & 15) * 2;
            *(float2*)&hiS[r][q] = *(const float2*)&g_hi [(size_t)(ib + r)*DD + hc + q];
            *(float2*)&hjS[r][q] = *(const float2*)&g_hjb[(size_t)(jb + r)*DD + hc + q];
        }
        __syncthreads();
#pragma unroll
        for (int hp = 0; hp < 16; hp++) {
            u64 wp = wsS[(hc >> 1) + hp];
            u64 ai[4], bj[4];
#pragma unroll
            for (int a = 0; a < 4; a++) {
                ai[a] = *(const u64*)&hiS[ig + a*16][hp*2];
                bj[a] = *(const u64*)&hjS[jg + a*16][hp*2];
            }
#pragma unroll
            for (int a = 0; a < 4; a++)
#pragma unroll
                for (int b = 0; b < 4; b++) {
                    u64 s = add2(ai[a], bj[b]) & amask;
                    acc[a][b] = fma2(s, wp, acc[a][b]);
                }
        }
    }

    float lsum = 0.f;
#pragma unroll
    for (int a = 0; a < 4; a++) {
        int i = ib + ig + a*16;
        float sia = siS[ig + a*16];
#pragma unroll
        for (int b = 0; b < 4; b++) {
            int j = jb + jg + b*16;
            float2 p = unpk(acc[a][b]);
            float lg = (p.x + p.y) + sia + sjS[jg + b*16];
            size_t off = (size_t)i*NN + j;
            out[off] = lg;
            float d = lg*adj[off] - ew[off];
            lsum = fmaf(d, d, lsum);
        }
    }

    red[t] = lsum;
    __syncthreads();
#pragma unroll
    for (int s = 128; s > 0; s >>= 1) {
        if (t < s) red[t] += red[t + s];
        __syncthreads();
    }
    if (t == 0) g_part[blockIdx.y*16 + blockIdx.x] = red[0];
}

// ---------------- final loss reduce ----------------
__global__ void loss_kernel(float* __restrict__ out_loss) {
    __shared__ float red[256];
    int t = threadIdx.x;
    red[t] = g_part[t];
    __syncthreads();
#pragma unroll
    for (int s = 128; s > 0; s >>= 1) {
        if (t < s) red[t] += red[t + s];
        __syncthreads();
    }
    if (t == 0) out_loss[0] = red[0] * (1.f / (1024.f * 1024.f));
}

// ---------------- launch ----------------
extern "C" void kernel_launch(void* const* d_in, const int* in_sizes, int n_in,
                              void* d_out, int out_size)
{
    const float* nf   = (const float*)d_in[0];
    const float* adj  = (const float*)d_in[1];
    const float* ew   = (const float*)d_in[2];
    const float* We   = (const float*)d_in[3];
    const float* be   = (const float*)d_in[4];
    const float* Wu   = (const float*)d_in[5];
    const float* bu   = (const float*)d_in[6];
    const float* Wv   = (const float*)d_in[7];
    const float* bv   = (const float*)d_in[8];
    const float* Wg   = (const float*)d_in[9];
    const float* bg   = (const float*)d_in[10];
    const float* Wc1  = (const float*)d_in[11];
    const float* bc1  = (const float*)d_in[12];
    const float* Wc2  = (const float*)d_in[13];
    const float* bc2  = (const float*)d_in[14];
    float* out = (float*)d_out;

    float *ph, *pu, *pv, *pagg, *phi, *phjb, *pP;
    cudaGetSymbolAddress((void**)&ph,   g_h);
    cudaGetSymbolAddress((void**)&pu,   g_u);
    cudaGetSymbolAddress((void**)&pv,   g_v);
    cudaGetSymbolAddress((void**)&pagg, g_agg);
    cudaGetSymbolAddress((void**)&phi,  g_hi);
    cudaGetSymbolAddress((void**)&phjb, g_hjb);
    cudaGetSymbolAddress((void**)&pP,   g_P);

    const int BIG = 1 << 30;

    embed_kernel<<<NN*DD/256, 256>>>(nf, We, be);

    for (int l = 0; l < NLAYERS; l++) {
        // u = h@Wu + bu ; v = h@Wv + bv
        gemm_kernel<<<dim3(32, 2, 1), 128>>>(ph, ph, BIG, DD,
                                             Wu + l*DD*DD, Wv + l*DD*DD,
                                             bu + l*DD,    bv + l*DD,
                                             pu, pv, DD);
        // agg partials = adj @ v  (split-K x4)
        gemm_kernel<<<dim3(32, 1, 4), 128>>>(adj, adj, BIG, NN,
                                             pv, pv, nullptr, nullptr,
                                             pP, pP, 256);
        agg_red_kernel<<<NN*DD/4/256, 256>>>();
        // gate partials: z=0 -> u@Wg[:D], z=1 -> agg@Wg[D:]
        gemm_kernel<<<dim3(32, 1, 2), 128>>>(pu, pagg, DD, DD,
                                             Wg + l*2*DD*DD, Wg + l*2*DD*DD,
                                             nullptr, nullptr,
                                             pP, pP, DD);
        gate_fin_kernel<<<NN*DD/4/256, 256>>>(bg + l*DD);
    }

    // hi = h@Wc1[:D] ; hjb = h@Wc1[D:] + bc1
    gemm_kernel<<<dim3(32, 2, 1), 128>>>(ph, ph, BIG, DD,
                                         Wc1, Wc1 + DD*DD,
                                         nullptr, bc1,
                                         phi, phjb, DD);

    sisj_kernel<<<dim3(128, 2), 256>>>(Wc2, bc2);
    cls_kernel<<<dim3(16, 16), 256>>>(Wc2, adj, ew, out);

    if (out_size > NN*NN) {
        loss_kernel<<<1, 256>>>(out + NN*NN);
    }
}

// round 7
// speedup vs baseline: 1.6947x; 1.2440x over previous
#include <cuda_runtime.h>

#define NN 1024
#define DD 128
#define NLAYERS 3

typedef unsigned long long u64;

// ---------------- f32x2 helpers ----------------
__device__ __forceinline__ u64 pack2(float x, float y){ u64 r; asm("mov.b64 %0,{%1,%2};":"=l"(r):"f"(x),"f"(y)); return r; }
__device__ __forceinline__ u64 dup2(float x){ return pack2(x, x); }
__device__ __forceinline__ u64 fma2(u64 a, u64 b, u64 c){ u64 d; asm("fma.rn.f32x2 %0,%1,%2,%3;":"=l"(d):"l"(a),"l"(b),"l"(c)); return d; }
__device__ __forceinline__ u64 add2(u64 a, u64 b){ u64 d; asm("add.rn.f32x2 %0,%1,%2;":"=l"(d):"l"(a),"l"(b)); return d; }
__device__ __forceinline__ float2 unpk(u64 x){ float2 f; asm("mov.b64 {%0,%1},%2;":"=f"(f.x),"=f"(f.y):"l"(x)); return f; }

// ---------------- scratch ----------------
__device__ float g_h  [NN*DD];
__device__ float g_u  [NN*DD];
__device__ float g_v  [NN*DD];
__device__ float g_hi [NN*DD];
__device__ float g_hjb[NN*DD];
__device__ float g_P  [4*NN*DD];   // agg split-K partials
__device__ float g_part[256];

// ---------------- embed: h = nf @ We + be ----------------
__global__ void embed_kernel(const float* __restrict__ nf,
                             const float* __restrict__ We,
                             const float* __restrict__ be) {
    int idx = blockIdx.x * blockDim.x + threadIdx.x;
    int i = idx >> 7, d = idx & 127;
    float a0 = nf[3*i], a1 = nf[3*i+1], a2 = nf[3*i+2];
    g_h[idx] = be[d] + a0*We[d] + a1*We[DD + d] + a2*We[2*DD + d];
}

// ---------------- dual-output GEMM: O = h @ B (+bias), K=DD ----------------
// tile 16 rows x 128 cols, 256 threads, thread tile 2r x 4c (f32x2).
// blockIdx.y selects (B1,bias1,O1)/(B2,bias2,O2). grid (64, 2).
__global__ __launch_bounds__(256, 4) void nn_gemm_kernel(
    const float* __restrict__ B1, const float* __restrict__ B2,
    const float* __restrict__ bias1, const float* __restrict__ bias2,
    float* __restrict__ O1, float* __restrict__ O2)
{
    __shared__ float As[32][18];     // [k][row]
    __shared__ float Bs[32][128];

    int t  = threadIdx.x;
    int rb = blockIdx.x * 16;
    const float* B    = blockIdx.y ? B2    : B1;
    const float* bias = blockIdx.y ? bias2 : bias1;
    float*       O    = blockIdx.y ? O2    : O1;

    int r0 = (t >> 5) * 2;           // warp-uniform -> broadcast LDS
    int c0 = (t & 31) * 4;

    u64 acc00 = 0, acc01 = 0, acc10 = 0, acc11 = 0;

    for (int kb = 0; kb < DD; kb += 32) {
        __syncthreads();
        if (t < 128) {
            int r = t >> 3, f4 = t & 7;
            float4 v = *(const float4*)&g_h[(size_t)(rb + r)*DD + kb + f4*4];
            As[f4*4+0][r] = v.x; As[f4*4+1][r] = v.y;
            As[f4*4+2][r] = v.z; As[f4*4+3][r] = v.w;
        }
#pragma unroll
        for (int e = 0; e < 4; e++) {
            int idx = e*256 + t;
            int k = idx >> 5, c4 = idx & 31;
            *(float4*)&Bs[k][c4*4] = *(const float4*)&B[(size_t)(kb + k)*DD + c4*4];
        }
        __syncthreads();
#pragma unroll
        for (int k = 0; k < 32; k++) {
            float2 a2 = *(const float2*)&As[k][r0];
            ulonglong2 b = *(const ulonglong2*)&Bs[k][c0];
            u64 d0 = dup2(a2.x), d1 = dup2(a2.y);
            acc00 = fma2(d0, b.x, acc00); acc01 = fma2(d0, b.y, acc01);
            acc10 = fma2(d1, b.x, acc10); acc11 = fma2(d1, b.y, acc11);
        }
    }

    u64 bb0 = 0ull, bb1 = 0ull;
    if (bias) {
        float4 u = *(const float4*)&bias[c0];
        bb0 = pack2(u.x, u.y); bb1 = pack2(u.z, u.w);
    }
    ulonglong2 s;
    s.x = add2(acc00, bb0); s.y = add2(acc01, bb1);
    *(ulonglong2*)&O[(size_t)(rb + r0)*DD + c0] = s;
    s.x = add2(acc10, bb0); s.y = add2(acc11, bb1);
    *(ulonglong2*)&O[(size_t)(rb + r0 + 1)*DD + c0] = s;
}

// ---------------- agg partials: P[z] = adj[:, z*256:(z+1)*256] @ v[z*256:...] ----------------
// tile 32 rows x 128 cols, 256 threads, thread tile 4r x 4c. grid (32, 1, 4).
__global__ __launch_bounds__(256, 2) void agg_gemm_kernel(const float* __restrict__ adj)
{
    __shared__ float As[32][36];     // [k][row]
    __shared__ float Bs[32][128];

    int t  = threadIdx.x;
    int rb = blockIdx.x * 32;
    int kstart = blockIdx.z * 256;

    int r0 = (t >> 5) * 4;           // warp-uniform
    int c0 = (t & 31) * 4;

    u64 acc[4][2];
#pragma unroll
    for (int r = 0; r < 4; r++) { acc[r][0] = 0ull; acc[r][1] = 0ull; }

    for (int kb = kstart; kb < kstart + 256; kb += 32) {
        __syncthreads();
        {
            int r = t >> 3, f4 = t & 7;
            float4 v = *(const float4*)&adj[(size_t)(rb + r)*NN + kb + f4*4];
            As[f4*4+0][r] = v.x; As[f4*4+1][r] = v.y;
            As[f4*4+2][r] = v.z; As[f4*4+3][r] = v.w;
        }
#pragma unroll
        for (int e = 0; e < 4; e++) {
            int idx = e*256 + t;
            int k = idx >> 5, c4 = idx & 31;
            *(float4*)&Bs[k][c4*4] = *(const float4*)&g_v[(size_t)(kb + k)*DD + c4*4];
        }
        __syncthreads();
#pragma unroll
        for (int k = 0; k < 32; k++) {
            float4 a4 = *(const float4*)&As[k][r0];
            ulonglong2 b = *(const ulonglong2*)&Bs[k][c0];
            u64 d0 = dup2(a4.x), d1 = dup2(a4.y), d2 = dup2(a4.z), d3 = dup2(a4.w);
            acc[0][0] = fma2(d0, b.x, acc[0][0]); acc[0][1] = fma2(d0, b.y, acc[0][1]);
            acc[1][0] = fma2(d1, b.x, acc[1][0]); acc[1][1] = fma2(d1, b.y, acc[1][1]);
            acc[2][0] = fma2(d2, b.x, acc[2][0]); acc[2][1] = fma2(d2, b.y, acc[2][1]);
            acc[3][0] = fma2(d3, b.x, acc[3][0]); acc[3][1] = fma2(d3, b.y, acc[3][1]);
        }
    }

    float* P = g_P + (size_t)blockIdx.z * (NN*DD);
#pragma unroll
    for (int r = 0; r < 4; r++) {
        ulonglong2 s; s.x = acc[r][0]; s.y = acc[r][1];
        *(ulonglong2*)&P[(size_t)(rb + r0 + r)*DD + c0] = s;
    }
}

// ---------------- fused gate: t = u@Wg[:D] + agg@Wg[D:] + bg ; h = relu(h + sigmoid(t)*agg) ----
// agg is summed inline from 4 split-K partials. tile 8 rows (warp-per-row) x 128 cols,
// 256 threads, K=256. grid 128.
__global__ __launch_bounds__(256, 2) void gate_kernel(
    const float* __restrict__ Wg, const float* __restrict__ bg)
{
    __shared__ float Au[8][DD];
    __shared__ float Ag[8][DD];
    __shared__ float Bs[32][DD];

    int t  = threadIdx.x;
    int rb = blockIdx.x * 8;
    int r  = t >> 5;                 // warp-per-row
    int f4 = t & 31;
    int c0 = f4 * 4;

    {
        size_t off = (size_t)(rb + r)*DD + f4*4;
        *(float4*)&Au[r][f4*4] = *(const float4*)&g_u[off];
        float4 p0 = *(const float4*)&g_P[off];
        float4 p1 = *(const float4*)&g_P[NN*DD + off];
        float4 p2 = *(const float4*)&g_P[2*NN*DD + off];
        float4 p3 = *(const float4*)&g_P[3*NN*DD + off];
        float4 s;
        s.x = (p0.x + p1.x) + (p2.x + p3.x);
        s.y = (p0.y + p1.y) + (p2.y + p3.y);
        s.z = (p0.z + p1.z) + (p2.z + p3.z);
        s.w = (p0.w + p1.w) + (p2.w + p3.w);
        *(float4*)&Ag[r][f4*4] = s;
    }

    u64 acc0 = 0ull, acc1 = 0ull;

    for (int kb = 0; kb < 2*DD; kb += 32) {
        __syncthreads();
#pragma unroll
        for (int e = 0; e < 4; e++) {
            int idx = e*256 + t;
            int k = idx >> 5, c4 = idx & 31;
            *(float4*)&Bs[k][c4*4] = *(const float4*)&Wg[(size_t)(kb + k)*DD + c4*4];
        }
        __syncthreads();
        const float* Arow = (kb < DD) ? Au[r] : Ag[r];
        int ko = (kb < DD) ? kb : kb - DD;
#pragma unroll
        for (int k = 0; k < 32; k++) {
            u64 d = dup2(Arow[ko + k]);          // broadcast LDS
            ulonglong2 b = *(const ulonglong2*)&Bs[k][c0];
            acc0 = fma2(d, b.x, acc0);
            acc1 = fma2(d, b.y, acc1);
        }
    }

    float4 bgv = *(const float4*)&bg[c0];
    float2 t01 = unpk(acc0), t23 = unpk(acc1);
    float tt[4] = {t01.x + bgv.x, t01.y + bgv.y, t23.x + bgv.z, t23.y + bgv.w};
    float4 ag = *(const float4*)&Ag[r][c0];
    float4 hv = *(const float4*)&g_h[(size_t)(rb + r)*DD + c0];
    float aa[4] = {ag.x, ag.y, ag.z, ag.w};
    float hh[4] = {hv.x, hv.y, hv.z, hv.w};
    float oo[4];
#pragma unroll
    for (int j = 0; j < 4; j++) {
        float g = 1.f / (1.f + __expf(-tt[j]));
        oo[j] = fmaxf(hh[j] + g * aa[j], 0.f);
    }
    *(float4*)&g_h[(size_t)(rb + r)*DD + c0] = make_float4(oo[0], oo[1], oo[2], oo[3]);
}

// ---------------- classifier + loss partials ----------------
// logits[i,j] = si[i] + sj[j] + sum_h |hi[i,h]+hjb[j,h]| * 0.5*w[h]
// si[i] = 0.5*dot(hi[i],w) ; sj[j] = 0.5*dot(hjb[j],w) + bc2 (computed inline).
__global__ __launch_bounds__(256, 2) void cls_kernel(
    const float* __restrict__ Wc2, const float* __restrict__ bc2,
    const float* __restrict__ adj, const float* __restrict__ ew,
    float* __restrict__ out)
{
    __shared__ float hiS[64][34];
    __shared__ float hjS[64][34];
    __shared__ u64   wsS[64];
    __shared__ float siS[64], sjS[64];
    __shared__ float red[256];

    int t  = threadIdx.x;
    int ib = blockIdx.y * 64, jb = blockIdx.x * 64;

    if (t < 128) {
        const float* row = (t < 64) ? &g_hi[(size_t)(ib + t)*DD]
                                    : &g_hjb[(size_t)(jb + t - 64)*DD];
        float s0 = 0.f, s1 = 0.f, s2 = 0.f, s3 = 0.f;
#pragma unroll
        for (int h = 0; h < DD; h += 4) {
            float4 v = *(const float4*)&row[h];
            float4 w = *(const float4*)&Wc2[h];
            s0 = fmaf(v.x, w.x, s0); s1 = fmaf(v.y, w.y, s1);
            s2 = fmaf(v.z, w.z, s2); s3 = fmaf(v.w, w.w, s3);
        }
        float s = 0.5f * ((s0 + s1) + (s2 + s3));
        if (t < 64) siS[t]      = s;
        else        sjS[t - 64] = s + bc2[0];
    } else if (t < 192) {
        int h2 = t - 128;
        wsS[h2] = pack2(0.5f*Wc2[2*h2], 0.5f*Wc2[2*h2+1]);
    }

    int ig = t >> 4, jg = t & 15;
    const u64 amask = 0x7FFFFFFF7FFFFFFFull;

    u64 acc[4][4];
#pragma unroll
    for (int a = 0; a < 4; a++)
#pragma unroll
        for (int b = 0; b < 4; b++) acc[a][b] = 0ull;

    for (int hc = 0; hc < DD; hc += 32) {
        __syncthreads();
#pragma unroll
        for (int e = 0; e < 4; e++) {
            int idx = e*256 + t;
            int r = idx >> 4, q = (idx & 15) * 2;
            *(float2*)&hiS[r][q] = *(const float2*)&g_hi [(size_t)(ib + r)*DD + hc + q];
            *(float2*)&hjS[r][q] = *(const float2*)&g_hjb[(size_t)(jb + r)*DD + hc + q];
        }
        __syncthreads();
#pragma unroll
        for (int hp = 0; hp < 16; hp++) {
            u64 wp = wsS[(hc >> 1) + hp];
            u64 ai[4], bj[4];
#pragma unroll
            for (int a = 0; a < 4; a++) {
                ai[a] = *(const u64*)&hiS[ig + a*16][hp*2];
                bj[a] = *(const u64*)&hjS[jg + a*16][hp*2];
            }
#pragma unroll
            for (int a = 0; a < 4; a++)
#pragma unroll
                for (int b = 0; b < 4; b++) {
                    u64 s = add2(ai[a], bj[b]) & amask;
                    acc[a][b] = fma2(s, wp, acc[a][b]);
                }
        }
    }

    float lsum = 0.f;
#pragma unroll
    for (int a = 0; a < 4; a++) {
        int i = ib + ig + a*16;
        float sia = siS[ig + a*16];
#pragma unroll
        for (int b = 0; b < 4; b++) {
            int j = jb + jg + b*16;
            float2 p = unpk(acc[a][b]);
            float lg = (p.x + p.y) + sia + sjS[jg + b*16];
            size_t off = (size_t)i*NN + j;
            out[off] = lg;
            float d = lg*adj[off] - ew[off];
            lsum = fmaf(d, d, lsum);
        }
    }

    red[t] = lsum;
    __syncthreads();
#pragma unroll
    for (int s = 128; s > 0; s >>= 1) {
        if (t < s) red[t] += red[t + s];
        __syncthreads();
    }
    if (t == 0) g_part[blockIdx.y*16 + blockIdx.x] = red[0];
}

// ---------------- final loss reduce ----------------
__global__ void loss_kernel(float* __restrict__ out_loss) {
    __shared__ float red[256];
    int t = threadIdx.x;
    red[t] = g_part[t];
    __syncthreads();
#pragma unroll
    for (int s = 128; s > 0; s >>= 1) {
        if (t < s) red[t] += red[t + s];
        __syncthreads();
    }
    if (t == 0) out_loss[0] = red[0] * (1.f / (1024.f * 1024.f));
}

// ---------------- launch ----------------
extern "C" void kernel_launch(void* const* d_in, const int* in_sizes, int n_in,
                              void* d_out, int out_size)
{
    const float* nf   = (const float*)d_in[0];
    const float* adj  = (const float*)d_in[1];
    const float* ew   = (const float*)d_in[2];
    const float* We   = (const float*)d_in[3];
    const float* be   = (const float*)d_in[4];
    const float* Wu   = (const float*)d_in[5];
    const float* bu   = (const float*)d_in[6];
    const float* Wv   = (const float*)d_in[7];
    const float* bv   = (const float*)d_in[8];
    const float* Wg   = (const float*)d_in[9];
    const float* bg   = (const float*)d_in[10];
    const float* Wc1  = (const float*)d_in[11];
    const float* bc1  = (const float*)d_in[12];
    const float* Wc2  = (const float*)d_in[13];
    const float* bc2  = (const float*)d_in[14];
    float* out = (float*)d_out;

    float *pu, *pv, *phi, *phjb;
    cudaGetSymbolAddress((void**)&pu,   g_u);
    cudaGetSymbolAddress((void**)&pv,   g_v);
    cudaGetSymbolAddress((void**)&phi,  g_hi);
    cudaGetSymbolAddress((void**)&phjb, g_hjb);

    embed_kernel<<<NN*DD/256, 256>>>(nf, We, be);

    for (int l = 0; l < NLAYERS; l++) {
        nn_gemm_kernel<<<dim3(64, 2), 256>>>(Wu + l*DD*DD, Wv + l*DD*DD,
                                             bu + l*DD,    bv + l*DD,
                                             pu, pv);
        agg_gemm_kernel<<<dim3(32, 1, 4), 256>>>(adj);
        gate_kernel<<<128, 256>>>(Wg + l*2*DD*DD, bg + l*DD);
    }

    nn_gemm_kernel<<<dim3(64, 2), 256>>>(Wc1, Wc1 + DD*DD,
                                         nullptr, bc1,
                                         phi, phjb);

    cls_kernel<<<dim3(16, 16), 256>>>(Wc2, bc2, adj, ew, out);

    if (out_size > NN*NN) {
        loss_kernel<<<1, 256>>>(out + NN*NN);
    }
}